// round 7
// baseline (speedup 1.0000x reference)
#include <cuda_runtime.h>

// out[i, c] = max_{k<7} x[hex_idx[i,k], c]  for i < L = out_size / 512
// hex_idx is int32 on disk (JAX downgrades int64 without x64 mode).
//
// At the LTS traffic floor (~168MB L2 traffic @ ~11.4TB/s -> ~14.8us).
// R7: 4 rows per 256-thread CTA (grid 2561) to cut one-shot CTA churn and
// raise sustained occupancy (10x4-warp CTAs couldn't be backfilled fast
// enough). Per-thread work unchanged: 7x 256-bit L2::evict_last gathers,
// 2x 128-bit streaming stores.

static constexpr int K = 7;

struct F8 { float f[8]; };

__device__ __forceinline__ F8 ldg_el_256(const char* base, unsigned off) {
    unsigned long long r0, r1, r2, r3;
    asm("ld.global.nc.L2::evict_last.v4.b64 {%0,%1,%2,%3}, [%4];"
        : "=l"(r0), "=l"(r1), "=l"(r2), "=l"(r3)
        : "l"(base + off));
    F8 v;
    v.f[0] = __uint_as_float((unsigned)(r0 & 0xffffffffu));
    v.f[1] = __uint_as_float((unsigned)(r0 >> 32));
    v.f[2] = __uint_as_float((unsigned)(r1 & 0xffffffffu));
    v.f[3] = __uint_as_float((unsigned)(r1 >> 32));
    v.f[4] = __uint_as_float((unsigned)(r2 & 0xffffffffu));
    v.f[5] = __uint_as_float((unsigned)(r2 >> 32));
    v.f[6] = __uint_as_float((unsigned)(r3 & 0xffffffffu));
    v.f[7] = __uint_as_float((unsigned)(r3 >> 32));
    return v;
}

__device__ __forceinline__ void stg_cs_128(float* p, float a, float b, float c, float d) {
    asm volatile("st.global.cs.v4.f32 [%0], {%1,%2,%3,%4};"
                 :: "l"(p), "f"(a), "f"(b), "f"(c), "f"(d)
                 : "memory");
}

__global__ void __launch_bounds__(256)
hex_pool_kernel(const char* __restrict__ x,      // (N, 2048 bytes) rows
                const int*  __restrict__ hex_idx,
                float*      __restrict__ out,    // (L, 512) floats
                int L)
{
    // 4 rows per CTA: warp-pair q (=tid>>6, 0..3) handles row 4*bid + q.
    const int q = threadIdx.x >> 6;         // 0..3
    const int c = threadIdx.x & 63;         // 32B chunk within row
    const int i = blockIdx.x * 4 + q;
    if (i >= L) return;

    const int* r = hex_idx + i * K;
    int j[K];
#pragma unroll
    for (int k = 0; k < K; k++) j[k] = __ldg(r + k);

    const unsigned coff = (unsigned)c * 32u;

    // 7 independent 256-bit gathers in flight before any consumption.
    F8 v[K];
#pragma unroll
    for (int k = 0; k < K; k++)
        v[k] = ldg_el_256(x, (unsigned)j[k] * 2048u + coff);

    float m[8];
#pragma unroll
    for (int e = 0; e < 8; e++) {
        float t = v[0].f[e];
#pragma unroll
        for (int k = 1; k < K; k++) t = fmaxf(t, v[k].f[e]);
        m[e] = t;
    }

    float* op = out + (unsigned)i * 512u + (unsigned)c * 8u;
    stg_cs_128(op,     m[0], m[1], m[2], m[3]);
    stg_cs_128(op + 4, m[4], m[5], m[6], m[7]);
}

extern "C" void kernel_launch(void* const* d_in, const int* in_sizes, int n_in,
                              void* d_out, int out_size)
{
    const char* x   = (const char*)d_in[0];  // (N, 512) float32 rows
    const int*  idx = (const int*)d_in[1];   // (N, 7) int32
    float*      out = (float*)d_out;         // (L, 512) float32

    int L = out_size / 512;                  // 10242
    int grid = (L + 3) / 4;                  // 2561 one-shot CTAs

    hex_pool_kernel<<<grid, 256>>>(x, idx, out, L);
}

// round 8
// speedup vs baseline: 1.0658x; 1.0658x over previous
#include <cuda_runtime.h>

// out[i, c] = max_{k<7} x[hex_idx[i,k], c]  for i < L = out_size / 512
// hex_idx is int32 on disk (JAX downgrades int64 without x64 mode).
//
// Structure (best, 14.8us = LTS structural cap: ~168MB L2 traffic @ ~11.3TB/s):
//   one-shot CTAs, 128 threads = 2 rows, 64 threads x 32B chunks per row,
//   7 independent 256-bit ld.global.nc.L2::evict_last gathers (x stays
//   L2-resident across graph replays), streaming stores (don't evict x).
// R8 micro: single 256-bit streaming store instead of 2x128-bit.

static constexpr int K = 7;

struct F8 { float f[8]; };

__device__ __forceinline__ F8 ldg_el_256(const char* base, unsigned off) {
    unsigned long long r0, r1, r2, r3;
    asm("ld.global.nc.L2::evict_last.v4.b64 {%0,%1,%2,%3}, [%4];"
        : "=l"(r0), "=l"(r1), "=l"(r2), "=l"(r3)
        : "l"(base + off));
    F8 v;
    v.f[0] = __uint_as_float((unsigned)(r0 & 0xffffffffu));
    v.f[1] = __uint_as_float((unsigned)(r0 >> 32));
    v.f[2] = __uint_as_float((unsigned)(r1 & 0xffffffffu));
    v.f[3] = __uint_as_float((unsigned)(r1 >> 32));
    v.f[4] = __uint_as_float((unsigned)(r2 & 0xffffffffu));
    v.f[5] = __uint_as_float((unsigned)(r2 >> 32));
    v.f[6] = __uint_as_float((unsigned)(r3 & 0xffffffffu));
    v.f[7] = __uint_as_float((unsigned)(r3 >> 32));
    return v;
}

__device__ __forceinline__ unsigned long long pack2(float lo, float hi) {
    return (unsigned long long)__float_as_uint(lo)
         | ((unsigned long long)__float_as_uint(hi) << 32);
}

__device__ __forceinline__ void stg_cs_256(float* p, const float* m) {
    asm volatile("st.global.cs.v4.b64 [%0], {%1,%2,%3,%4};"
                 :: "l"(p),
                    "l"(pack2(m[0], m[1])), "l"(pack2(m[2], m[3])),
                    "l"(pack2(m[4], m[5])), "l"(pack2(m[6], m[7]))
                 : "memory");
}

__global__ void __launch_bounds__(128)
hex_pool_kernel(const char* __restrict__ x,      // (N, 2048 bytes) rows
                const int*  __restrict__ hex_idx,
                float*      __restrict__ out,    // (L, 512) floats
                int L)
{
    // 2 rows per CTA: threads 0..63 -> row 2b, 64..127 -> row 2b+1.
    const int half = threadIdx.x >> 6;      // 0 or 1
    const int c    = threadIdx.x & 63;      // 32B chunk within row
    const int i    = blockIdx.x * 2 + half;
    if (i >= L) return;

    const int* r = hex_idx + i * K;
    int j[K];
#pragma unroll
    for (int k = 0; k < K; k++) j[k] = __ldg(r + k);

    const unsigned coff = (unsigned)c * 32u;

    // 7 independent 256-bit gathers in flight before any consumption.
    F8 v[K];
#pragma unroll
    for (int k = 0; k < K; k++)
        v[k] = ldg_el_256(x, (unsigned)j[k] * 2048u + coff);

    float m[8];
#pragma unroll
    for (int e = 0; e < 8; e++) {
        float t = v[0].f[e];
#pragma unroll
        for (int k = 1; k < K; k++) t = fmaxf(t, v[k].f[e]);
        m[e] = t;
    }

    stg_cs_256(out + (unsigned)i * 512u + (unsigned)c * 8u, m);
}

extern "C" void kernel_launch(void* const* d_in, const int* in_sizes, int n_in,
                              void* d_out, int out_size)
{
    const char* x   = (const char*)d_in[0];  // (N, 512) float32 rows
    const int*  idx = (const int*)d_in[1];   // (N, 7) int32
    float*      out = (float*)d_out;         // (L, 512) float32

    int L = out_size / 512;                  // 10242
    int grid = (L + 1) / 2;                  // 5121 one-shot CTAs

    hex_pool_kernel<<<grid, 128>>>(x, idx, out, L);
}

// round 9
// speedup vs baseline: 1.0866x; 1.0195x over previous
#include <cuda_runtime.h>

// out[i, c] = max_{k<7} x[hex_idx[i,k], c]  for i < L = out_size / 512
// hex_idx is int32 on disk (JAX downgrades int64 without x64 mode).
//
// Structure (best, ~14.8us = LTS structural cap: ~168MB L2 traffic @ ~11.3TB/s):
//   one-shot CTAs, 128 threads = 2 rows, 64 threads x 32B chunks per row,
//   7 independent 256-bit gathers, 2x128-bit streaming stores (.cs keeps the
//   write stream from evicting x). R9 A/B: drop the L2::evict_last hint
//   (plain ld.global.nc.v4.b64) — .cs on stores should preserve x residency
//   via default LRU; tests whether the policy tag itself costs anything.

static constexpr int K = 7;

struct F8 { float f[8]; };

__device__ __forceinline__ F8 ldg_nc_256(const char* base, unsigned off) {
    unsigned long long r0, r1, r2, r3;
    asm("ld.global.nc.v4.b64 {%0,%1,%2,%3}, [%4];"
        : "=l"(r0), "=l"(r1), "=l"(r2), "=l"(r3)
        : "l"(base + off));
    F8 v;
    v.f[0] = __uint_as_float((unsigned)(r0 & 0xffffffffu));
    v.f[1] = __uint_as_float((unsigned)(r0 >> 32));
    v.f[2] = __uint_as_float((unsigned)(r1 & 0xffffffffu));
    v.f[3] = __uint_as_float((unsigned)(r1 >> 32));
    v.f[4] = __uint_as_float((unsigned)(r2 & 0xffffffffu));
    v.f[5] = __uint_as_float((unsigned)(r2 >> 32));
    v.f[6] = __uint_as_float((unsigned)(r3 & 0xffffffffu));
    v.f[7] = __uint_as_float((unsigned)(r3 >> 32));
    return v;
}

__device__ __forceinline__ void stg_cs_128(float* p, float a, float b, float c, float d) {
    asm volatile("st.global.cs.v4.f32 [%0], {%1,%2,%3,%4};"
                 :: "l"(p), "f"(a), "f"(b), "f"(c), "f"(d)
                 : "memory");
}

__global__ void __launch_bounds__(128)
hex_pool_kernel(const char* __restrict__ x,      // (N, 2048 bytes) rows
                const int*  __restrict__ hex_idx,
                float*      __restrict__ out,    // (L, 512) floats
                int L)
{
    // 2 rows per CTA: threads 0..63 -> row 2b, 64..127 -> row 2b+1.
    const int half = threadIdx.x >> 6;      // 0 or 1
    const int c    = threadIdx.x & 63;      // 32B chunk within row
    const int i    = blockIdx.x * 2 + half;
    if (i >= L) return;

    const int* r = hex_idx + i * K;
    int j[K];
#pragma unroll
    for (int k = 0; k < K; k++) j[k] = __ldg(r + k);

    const unsigned coff = (unsigned)c * 32u;

    // 7 independent 256-bit gathers in flight before any consumption.
    F8 v[K];
#pragma unroll
    for (int k = 0; k < K; k++)
        v[k] = ldg_nc_256(x, (unsigned)j[k] * 2048u + coff);

    float m[8];
#pragma unroll
    for (int e = 0; e < 8; e++) {
        float t = v[0].f[e];
#pragma unroll
        for (int k = 1; k < K; k++) t = fmaxf(t, v[k].f[e]);
        m[e] = t;
    }

    float* op = out + (unsigned)i * 512u + (unsigned)c * 8u;
    stg_cs_128(op,     m[0], m[1], m[2], m[3]);
    stg_cs_128(op + 4, m[4], m[5], m[6], m[7]);
}

extern "C" void kernel_launch(void* const* d_in, const int* in_sizes, int n_in,
                              void* d_out, int out_size)
{
    const char* x   = (const char*)d_in[0];  // (N, 512) float32 rows
    const int*  idx = (const int*)d_in[1];   // (N, 7) int32
    float*      out = (float*)d_out;         // (L, 512) float32

    int L = out_size / 512;                  // 10242
    int grid = (L + 1) / 2;                  // 5121 one-shot CTAs

    hex_pool_kernel<<<grid, 128>>>(x, idx, out, L);
}